// round 17
// baseline (speedup 1.0000x reference)
#include <cuda_runtime.h>
#include <cuda_fp16.h>
#include <cstdint>

// ---------------- problem constants ----------------
#define TOKENS 4096
#define IN_F   4096
#define OUT_F  11008
#define NGRP   32

// ---------------- tile config ----------------
#define BM 128
#define BN 64                    // CTA tile 128x64
#define NSTEP (IN_F / 16)        // 256 k-steps of 16
#define STEP_HALVES 2048         // halves per (128-row, 16-k) fragment slab
#define TILE_HALVES ((size_t)NSTEP * STEP_HALVES)
#define NTHREADS 128             // 4 warps: 2x2 grid of 64x32 warp tiles

#define PREPX_BLOCKS 8192        // (TOKENS * IN_F/8) / 256
#define PREPW_BLOCKS 22016       // (OUT_F  * IN_F/8) / 256

// ---------------- persistent scratch ----------------
__device__ __half g_xs[(size_t)TOKENS * IN_F];    // x fp16, A-fragment-tiled
__device__ __half g_wd[(size_t)OUT_F * IN_F];     // W dequant fp16, B-fragment-tiled

__device__ __forceinline__ void mma16(float& d0, float& d1, float& d2, float& d3,
                                      uint32_t a0, uint32_t a1, uint32_t a2, uint32_t a3,
                                      uint32_t b0, uint32_t b1) {
    asm volatile("mma.sync.aligned.m16n8k16.row.col.f32.f16.f16.f32 "
                 "{%0,%1,%2,%3}, {%4,%5,%6,%7}, {%8,%9}, {%0,%1,%2,%3};"
                 : "+f"(d0), "+f"(d1), "+f"(d2), "+f"(d3)
                 : "r"(a0), "r"(a1), "r"(a2), "r"(a3), "r"(b0), "r"(b1));
}

__device__ __forceinline__ void stg_cs_v2(float* p, float a, float b) {
    asm volatile("st.global.cs.v2.f32 [%0], {%1, %2};" :: "l"(p), "f"(a), "f"(b) : "memory");
}

// ============ fused prepass (byte-identical outputs to R8..R16 passing versions) ============
__global__ void __launch_bounds__(256)
prep_fused_kernel(const float* __restrict__ x,
                  const int*   __restrict__ wp,
                  const float* __restrict__ ws,
                  const int*   __restrict__ wz)
{
    if (blockIdx.x < PREPX_BLOCKS) {
        const int gid  = blockIdx.x * 256 + threadIdx.x;
        const int lane = gid & 31;
        const int blk  = (gid >> 5) & 31;          // ks*8 + mb within 64-k chunk
        const int stg  = gid >> 10;                // mt*64 + chunk
        const int chunk = stg & 63;
        const int mt   = stg >> 6;
        const int ks = blk >> 3, mb = blk & 7;
        const int m = mt * 128 + mb * 16 + (lane >> 2);
        const int k = chunk * 64 + ks * 16 + (lane & 3) * 2;

        const float* xr = x + (size_t)m * IN_F + k;
        const float2 v0 = *(const float2*)(xr);
        const float2 v1 = *(const float2*)(xr + (size_t)8 * IN_F);
        const float2 v2 = *(const float2*)(xr + 8);
        const float2 v3 = *(const float2*)(xr + (size_t)8 * IN_F + 8);

        __half2 h0 = __floats2half2_rn(v0.x, v0.y);
        __half2 h1 = __floats2half2_rn(v1.x, v1.y);
        __half2 h2 = __floats2half2_rn(v2.x, v2.y);
        __half2 h3 = __floats2half2_rn(v3.x, v3.y);

        uint4 o;
        o.x = *(uint32_t*)&h0; o.y = *(uint32_t*)&h1;
        o.z = *(uint32_t*)&h2; o.w = *(uint32_t*)&h3;
        *(uint4*)(g_xs + (size_t)mt * TILE_HALVES
                  + (size_t)(chunk * 4 + ks) * STEP_HALVES + mb * 256 + lane * 8) = o;
    } else {
        const int gid  = (blockIdx.x - PREPX_BLOCKS) * 256 + threadIdx.x;
        const int lane = gid & 31;
        const int blk  = (gid >> 5) & 31;
        const int stg  = gid >> 10;                // nt128*64 + chunk
        const int chunk = stg & 63;
        const int nt   = stg >> 6;
        const int ks = blk >> 3, np = blk & 7;
        const int n = nt * 128 + np * 16 + (lane >> 2);
        const int k = chunk * 64 + ks * 16 + (lane & 3) * 2;
        const int grp = k >> 7;

        const int* r0 = wp + (size_t)n * 2048;     // one packed byte per int32
        const int* r1 = r0 + (size_t)8 * 2048;
        const int i0 = k >> 1;
        const int b00 = r0[i0], b01 = r0[i0 + 4];
        const int b10 = r1[i0], b11 = r1[i0 + 4];

        const float s0 = ws[(size_t)n * NGRP + grp];
        const float c0 = (-8.0f - (float)wz[(size_t)n * NGRP + grp]) * s0;
        const float s1 = ws[(size_t)(n + 8) * NGRP + grp];
        const float c1 = (-8.0f - (float)wz[(size_t)(n + 8) * NGRP + grp]) * s1;

        #define DQ(b, sh, s, c) fmaf((float)(int)((((uint32_t)(b) >> (sh)) & 15u) ^ 8u), (s), (c))
        __half2 h0 = __floats2half2_rn(DQ(b00, 0, s0, c0), DQ(b00, 4, s0, c0));
        __half2 h1 = __floats2half2_rn(DQ(b01, 0, s0, c0), DQ(b01, 4, s0, c0));
        __half2 h2 = __floats2half2_rn(DQ(b10, 0, s1, c1), DQ(b10, 4, s1, c1));
        __half2 h3 = __floats2half2_rn(DQ(b11, 0, s1, c1), DQ(b11, 4, s1, c1));
        #undef DQ

        uint4 o;
        o.x = *(uint32_t*)&h0; o.y = *(uint32_t*)&h1;
        o.z = *(uint32_t*)&h2; o.w = *(uint32_t*)&h3;
        *(uint4*)(g_wd + (size_t)nt * TILE_HALVES
                  + (size_t)(chunk * 4 + ks) * STEP_HALVES + np * 256 + lane * 8) = o;
    }
}

// ============ main GEMM: 128x64 CTA, 64x32 warp tiles, running-pointer LDG streams ============
#define MMA_BURST(A, B)                                                              \
    _Pragma("unroll")                                                                \
    for (int mf = 0; mf < 4; mf++)                                                   \
        _Pragma("unroll")                                                            \
        for (int p = 0; p < 2; p++) {                                                \
            mma16(acc[mf][2*p][0], acc[mf][2*p][1], acc[mf][2*p][2], acc[mf][2*p][3],\
                  A[mf].x, A[mf].y, A[mf].z, A[mf].w, B[p].x, B[p].y);               \
            mma16(acc[mf][2*p+1][0], acc[mf][2*p+1][1],                              \
                  acc[mf][2*p+1][2], acc[mf][2*p+1][3],                              \
                  A[mf].x, A[mf].y, A[mf].z, A[mf].w, B[p].z, B[p].w);               \
        }

__global__ void __launch_bounds__(NTHREADS, 4)
gemm_kernel(float* __restrict__ y)
{
    const int tid  = threadIdx.x;
    const int lane = tid & 31;
    const int wid  = tid >> 5;
    const int warprow = wid >> 1;       // 0..1  (64 m)
    const int warpcol = wid & 1;        // 0..1  (32 n)
    const int mt = blockIdx.x;          // 0..31, fastest: co-resident CTAs share nt
    const int nt = blockIdx.y;          // 0..171 (64-wide n tiles)

    const __half* Abase = g_xs + (size_t)mt * TILE_HALVES
                        + (size_t)(warprow * 4) * 256 + (size_t)lane * 8;
    const __half* Bbase = g_wd + (size_t)(nt >> 1) * TILE_HALVES
                        + (size_t)(((nt & 1) * 4 + warpcol * 2)) * 256 + (size_t)lane * 8;

    float acc[4][4][4];
    #pragma unroll
    for (int mf = 0; mf < 4; mf++)
        #pragma unroll
        for (int f = 0; f < 4; f++)
            #pragma unroll
            for (int q = 0; q < 4; q++) acc[mf][f][q] = 0.0f;

    uint4 aEv[4], aOd[4], bEv[2], bOd[2];
    #pragma unroll
    for (int mf = 0; mf < 4; mf++) aEv[mf] = __ldg((const uint4*)(Abase + mf * 256));
    #pragma unroll
    for (int p = 0; p < 2; p++)    bEv[p]  = __ldg((const uint4*)(Bbase + p * 256));

    // running pointers: next slab to load (start at s = 1)
    const __half* An = Abase + STEP_HALVES;
    const __half* Bn = Bbase + STEP_HALVES;

    // steady state (no tail branch): pairs s = 0..NSTEP-4
    for (int s = 0; s < NSTEP - 2; s += 2) {
        #pragma unroll
        for (int mf = 0; mf < 4; mf++) aOd[mf] = __ldg((const uint4*)(An + mf * 256));
        #pragma unroll
        for (int p = 0; p < 2; p++)    bOd[p]  = __ldg((const uint4*)(Bn + p * 256));
        An += STEP_HALVES; Bn += STEP_HALVES;
        MMA_BURST(aEv, bEv)
        #pragma unroll
        for (int mf = 0; mf < 4; mf++) aEv[mf] = __ldg((const uint4*)(An + mf * 256));
        #pragma unroll
        for (int p = 0; p < 2; p++)    bEv[p]  = __ldg((const uint4*)(Bn + p * 256));
        An += STEP_HALVES; Bn += STEP_HALVES;
        MMA_BURST(aOd, bOd)
    }

    // peeled final 2 steps (s = NSTEP-2, NSTEP-1); An/Bn point at slab NSTEP-1
    {
        #pragma unroll
        for (int mf = 0; mf < 4; mf++) aOd[mf] = __ldg((const uint4*)(An + mf * 256));
        #pragma unroll
        for (int p = 0; p < 2; p++)    bOd[p]  = __ldg((const uint4*)(Bn + p * 256));
        MMA_BURST(aEv, bEv)
        MMA_BURST(aOd, bOd)
    }

    // ---- epilogue: streaming stores ----
    const int g = lane >> 2, t = lane & 3;
    const int m0 = mt * BM, n0 = nt * BN;
    #pragma unroll
    for (int mf = 0; mf < 4; mf++) {
        const int row0 = m0 + warprow * 64 + mf * 16 + g;
        #pragma unroll
        for (int f = 0; f < 4; f++) {
            // f = 2*p + o: n-pair p (16 n), within-pair o (8 n)
            const int ncol = n0 + warpcol * 32 + (f >> 1) * 16 + (f & 1) * 8 + 2 * t;
            float* p0 = y + (size_t)row0 * OUT_F + ncol;
            float* p1 = p0 + (size_t)8 * OUT_F;
            stg_cs_v2(p0, acc[mf][f][0], acc[mf][f][1]);
            stg_cs_v2(p1, acc[mf][f][2], acc[mf][f][3]);
        }
    }
}

extern "C" void kernel_launch(void* const* d_in, const int* in_sizes, int n_in,
                              void* d_out, int out_size)
{
    const float* x  = (const float*)d_in[0];
    const int*   wp = (const int*)d_in[1];
    const float* ws = (const float*)d_in[2];
    const int*   wz = (const int*)d_in[3];
    float*       y  = (float*)d_out;

    prep_fused_kernel<<<PREPX_BLOCKS + PREPW_BLOCKS, 256>>>(x, wp, ws, wz);
    gemm_kernel<<<dim3(TOKENS / BM, OUT_F / BN), NTHREADS>>>(y);
}